// round 6
// baseline (speedup 1.0000x reference)
#include <cuda_runtime.h>

// P1 vector FEM eval on structured 16x16 triangulated unit square.
// Bit-faithful numerics (R4): exact fp32 classification, interior-gridline
// bbox exclusion, argmax tie -> upper triangle, reference op-order output.
//
// Perf (R6): 2 points/thread via float4 LDG/STG (single wave: 128 blocks x
// 256 thr on 148 SMs), NO smem stage -- weight gathers go through L1 (warm
// across graph replays; ~600B working set), removing the __syncthreads and
// the weight-fill instructions from the critical path.

__device__ __forceinline__ void eval_point(
    float px, float py,
    const float* __restrict__ wx, const float* __restrict__ wy,
    float& ox, float& oy)
{
    const float NTOL = -1e-10f;

    float fx = __fmul_rn(px, 16.0f);    // exact
    float fy = __fmul_rn(py, 16.0f);
    int i = (int)floorf(fx);
    int j = (int)floorf(fy);
    i = min(max(i, 0), 15);
    j = min(max(j, 0), 15);

    float u = __fsub_rn(fx, (float)i);  // exact
    float v = __fsub_rn(fy, (float)j);  // exact

    // reference-faithful inside tests (exact fp32)
    float P  = __fsub_rn(fx, fy);                 // fl(16px - 16py)
    float s1 = __fsub_rn(P, (float)(i - j));      // T1 s
    float t2 = -s1;                               // T2 t (bitwise)

    bool in1 = (s1 > NTOL) && (v > NTOL) && (__fadd_rn(s1, v) < 1.0f);
    bool in2 = (u  > NTOL) && (t2 > NTOL) && (__fadd_rn(u, t2) < 1.0f);

    // interior gridline points fail every strict bbox in the reference
    bool on_g = ((u == 0.0f) && (i > 0)) || ((v == 0.0f) && (j > 0));
    bool hit = (px >= 0.0f) && (px < 1.0f) && (py >= 0.0f) && (py < 1.0f) &&
               !on_g && (in1 || in2);

    // branchless triangle select (argmax tie -> T2)
    int v00 = i * 17 + j;
    float s  = in2 ? u : __fsub_rn(u, v);
    float t  = in2 ? __fsub_rn(v, u) : v;
    int  k1  = in2 ? (v00 + 18) : (v00 + 17);
    int  k2  = in2 ? (v00 + 1)  : (v00 + 18);
    float b0 = __fsub_rn(__fsub_rn(1.0f, s), t);

    float w0x = __ldg(wx + v00), w1x = __ldg(wx + k1), w2x = __ldg(wx + k2);
    float w0y = __ldg(wy + v00), w1y = __ldg(wy + k1), w2y = __ldg(wy + k2);

    float rx = __fadd_rn(__fadd_rn(__fmul_rn(b0, w0x), __fmul_rn(s, w1x)),
                         __fmul_rn(t, w2x));
    float ry = __fadd_rn(__fadd_rn(__fmul_rn(b0, w0y), __fmul_rn(s, w1y)),
                         __fmul_rn(t, w2y));
    ox = hit ? rx : 0.0f;
    oy = hit ? ry : 0.0f;
}

__global__ void __launch_bounds__(256)
p1_eval_kernel(const float4* __restrict__ pts4,
               const float*  __restrict__ wx,
               const float*  __restrict__ wy,
               float4* __restrict__ out4)
{
    int gid = blockIdx.x * blockDim.x + threadIdx.x;

    float4 pp = pts4[gid];   // two points: (x0,y0,x1,y1)

    float4 r;
    eval_point(pp.x, pp.y, wx, wy, r.x, r.y);
    eval_point(pp.z, pp.w, wx, wy, r.z, r.w);

    out4[gid] = r;
}

extern "C" void kernel_launch(void* const* d_in, const int* in_sizes, int n_in,
                              void* d_out, int out_size)
{
    const float4* pts4 = (const float4*)d_in[0];
    const float*  wx   = (const float*)d_in[1];
    const float*  wy   = (const float*)d_in[2];
    float4* out4 = (float4*)d_out;

    // 65536 points -> 32768 float4 -> 128 blocks x 256 threads (one wave)
    int n4 = (in_sizes[0] / 2) / 2;
    int threads = 256;
    int blocks = n4 / threads;
    p1_eval_kernel<<<blocks, threads>>>(pts4, wx, wy, out4);
}

// round 7
// speedup vs baseline: 1.0386x; 1.0386x over previous
#include <cuda_runtime.h>

// P1 vector FEM eval on structured 16x16 triangulated unit square.
// Bit-faithful numerics (R4): exact fp32 classification, interior-gridline
// bbox exclusion, argmax tie -> upper triangle, reference op-order output.
//
// Perf (R7 = best-of-R5 + block geometry): 2 points/thread via float4
// LDG/STG; weights staged in smem as interleaved (wx,wy) float2 pairs
// (R6 showed scattered LDG gathers are slower than smem broadcast);
// 128-thread blocks x 256 CTAs so co-resident CTAs hide each other's
// smem-fill barrier wait.

__device__ __forceinline__ void eval_point(
    float px, float py, const float2* __restrict__ w, float& ox, float& oy)
{
    const float NTOL = -1e-10f;

    float fx = __fmul_rn(px, 16.0f);    // exact
    float fy = __fmul_rn(py, 16.0f);
    int i = (int)floorf(fx);
    int j = (int)floorf(fy);
    i = min(max(i, 0), 15);
    j = min(max(j, 0), 15);

    float u = __fsub_rn(fx, (float)i);  // exact
    float v = __fsub_rn(fy, (float)j);  // exact

    // reference-faithful inside tests (exact fp32)
    float P  = __fsub_rn(fx, fy);                 // fl(16px - 16py)
    float s1 = __fsub_rn(P, (float)(i - j));      // T1 s
    float t2 = -s1;                               // T2 t (bitwise)

    bool in1 = (s1 > NTOL) && (v > NTOL) && (__fadd_rn(s1, v) < 1.0f);
    bool in2 = (u  > NTOL) && (t2 > NTOL) && (__fadd_rn(u, t2) < 1.0f);

    // interior gridline points fail every strict bbox in the reference
    bool on_g = ((u == 0.0f) && (i > 0)) || ((v == 0.0f) && (j > 0));
    bool hit = (px >= 0.0f) && (px < 1.0f) && (py >= 0.0f) && (py < 1.0f) &&
               !on_g && (in1 || in2);

    // branchless triangle select (argmax tie -> T2)
    int v00 = i * 17 + j;
    float s  = in2 ? u : __fsub_rn(u, v);
    float t  = in2 ? __fsub_rn(v, u) : v;
    int  k1  = in2 ? (v00 + 18) : (v00 + 17);
    int  k2  = in2 ? (v00 + 1)  : (v00 + 18);
    float b0 = __fsub_rn(__fsub_rn(1.0f, s), t);

    float2 w0 = w[v00];
    float2 w1 = w[k1];
    float2 w2 = w[k2];

    float rx = __fadd_rn(__fadd_rn(__fmul_rn(b0, w0.x), __fmul_rn(s, w1.x)),
                         __fmul_rn(t, w2.x));
    float ry = __fadd_rn(__fadd_rn(__fmul_rn(b0, w0.y), __fmul_rn(s, w1.y)),
                         __fmul_rn(t, w2.y));
    ox = hit ? rx : 0.0f;
    oy = hit ? ry : 0.0f;
}

__global__ void __launch_bounds__(128)
p1_eval_kernel(const float4* __restrict__ pts4,
               const float*  __restrict__ wx,
               const float*  __restrict__ wy,
               float4* __restrict__ out4)
{
    __shared__ float2 wsh[289];

    int tid = threadIdx.x;
    int gid = blockIdx.x * blockDim.x + tid;

    // issue the (independent) point load first so it overlaps the smem fill
    float4 pp = pts4[gid];   // two points: (x0,y0,x1,y1)

    // stage weights interleaved; 289 = 2*128 + 33 -> 3 predicated steps
    wsh[tid]        = make_float2(__ldg(wx + tid),       __ldg(wy + tid));
    wsh[tid + 128]  = make_float2(__ldg(wx + tid + 128), __ldg(wy + tid + 128));
    if (tid < 33)
        wsh[tid + 256] = make_float2(__ldg(wx + tid + 256),
                                     __ldg(wy + tid + 256));
    __syncthreads();

    float4 r;
    eval_point(pp.x, pp.y, wsh, r.x, r.y);
    eval_point(pp.z, pp.w, wsh, r.z, r.w);

    out4[gid] = r;
}

extern "C" void kernel_launch(void* const* d_in, const int* in_sizes, int n_in,
                              void* d_out, int out_size)
{
    const float4* pts4 = (const float4*)d_in[0];
    const float*  wx   = (const float*)d_in[1];
    const float*  wy   = (const float*)d_in[2];
    float4* out4 = (float4*)d_out;

    // 65536 points -> 32768 float4 -> 256 blocks x 128 threads
    int n4 = (in_sizes[0] / 2) / 2;
    int threads = 128;
    int blocks = n4 / threads;
    p1_eval_kernel<<<blocks, threads>>>(pts4, wx, wy, out4);
}